// round 12
// baseline (speedup 1.0000x reference)
#include <cuda_runtime.h>
#include <cuda_fp16.h>

#define Dd 96
#define Hh 160
#define Ww 160
#define DHW (Dd*Hh*Ww)

// composed-flow scratch:
//  zy dup-pair: uint2 = { half2(z_i,y_i), half2(z_{i+1},y_{i+1}) }
//  x  dup-pair: half2 = ( x_i, x_{i+1} ),  neighbor clamped at W-1
__device__ uint2   g_Pzy[DHW];
__device__ __half2 g_Px [DHW];
__device__ uint2   g_Qzy[DHW];
__device__ __half2 g_Qx [DHW];
__device__ __half2 g_S  [DHW];   // src dup-pair fp16

// coord(v,s) = v*s/(s-1) - 0.5
#define SZC ((float)Dd / (float)(Dd - 1))
#define SYC ((float)Hh / (float)(Hh - 1))
#define SXC ((float)Ww / (float)(Ww - 1))

__device__ __forceinline__ void stcs2(float* p, float a, float b) {
    asm volatile("st.global.cs.v2.f32 [%0], {%1, %2};" :: "l"(p), "f"(a), "f"(b) : "memory");
}
__device__ __forceinline__ void stcs4(void* p, uint4 v) {
    asm volatile("st.global.cs.v4.b32 [%0], {%1, %2, %3, %4};"
                 :: "l"(p), "r"(v.x), "r"(v.y), "r"(v.z), "r"(v.w) : "memory");
}

// Dup-pair corner setup: 4 row offsets (x folded in), row weights, pair weights.
__device__ __forceinline__ void dup_corners(float cz, float cy, float cx,
                                            int ro[4], float wyz[4],
                                            float& wa, float& wb) {
    float zf = floorf(cz), yf = floorf(cy), xf = floorf(cx);
    float tz = cz - zf, ty = cy - yf, tx = cx - xf;
    int z0 = (int)zf, y0 = (int)yf, x0 = (int)xf;

    float wz0 = (z0 >= 0     && z0 < Dd)     ? (1.f - tz) : 0.f;
    float wz1 = (z0 + 1 >= 0 && z0 + 1 < Dd) ? tz         : 0.f;
    float wy0 = (y0 >= 0     && y0 < Hh)     ? (1.f - ty) : 0.f;
    float wy1 = (y0 + 1 >= 0 && y0 + 1 < Hh) ? ty         : 0.f;
    float wx0 = (x0 >= 0     && x0 < Ww)     ? (1.f - tx) : 0.f;
    float wx1 = (x0 + 1 >= 0 && x0 + 1 < Ww) ? tx         : 0.f;

    wa = (x0 >= 0) ? wx0 : wx1;     // dup[0].lo == v[0] when x0 == -1
    wb = (x0 >= 0) ? wx1 : 0.f;
    int xc = min(max(x0, 0), Ww - 1);

    int z0c = min(max(z0, 0), Dd - 1), z1c = min(max(z0 + 1, 0), Dd - 1);
    int y0c = min(max(y0, 0), Hh - 1), y1c = min(max(y0 + 1, 0), Hh - 1);

    ro[0] = (z0c * Hh + y0c) * Ww + xc;  wyz[0] = wz0 * wy0;
    ro[1] = (z0c * Hh + y1c) * Ww + xc;  wyz[1] = wz0 * wy1;
    ro[2] = (z1c * Hh + y0c) * Ww + xc;  wyz[2] = wz1 * wy0;
    ro[3] = (z1c * Hh + y1c) * Ww + xc;  wyz[3] = wz1 * wy1;
}

__device__ __forceinline__ void gather_packed(
        const uint2* __restrict__ zy, const __half2* __restrict__ px,
        const int ro[4], const float wyz[4], float wa, float wb,
        float& vz, float& vy, float& vx) {
    vz = 0.f; vy = 0.f; vx = 0.f;
    #pragma unroll
    for (int r = 0; r < 4; r++) {
        uint2 u = __ldg(zy + ro[r]);
        float2 a = __half22float2(*reinterpret_cast<__half2*>(&u.x));
        float2 b = __half22float2(*reinterpret_cast<__half2*>(&u.y));
        vz = fmaf(wyz[r], fmaf(wb, b.x, wa * a.x), vz);
        vy = fmaf(wyz[r], fmaf(wb, b.y, wa * a.y), vy);
        float2 c = __half22float2(__ldg(px + ro[r]));
        vx = fmaf(wyz[r], fmaf(wb, c.y, wa * c.x), vx);
    }
}

// fp32 planar 8-corner setup (flow0 gather in step1)
__device__ __forceinline__ void make_corners(float cz, float cy, float cx,
                                             int off[8], float w[8]) {
    float z0f = floorf(cz), y0f = floorf(cy), x0f = floorf(cx);
    float tz = cz - z0f, ty = cy - y0f, tx = cx - x0f;
    int z0 = (int)z0f, y0 = (int)y0f, x0 = (int)x0f;

    float wz0 = (z0 >= 0     && z0 < Dd)     ? (1.f - tz) : 0.f;
    float wz1 = (z0 + 1 >= 0 && z0 + 1 < Dd) ? tz         : 0.f;
    float wy0 = (y0 >= 0     && y0 < Hh)     ? (1.f - ty) : 0.f;
    float wy1 = (y0 + 1 >= 0 && y0 + 1 < Hh) ? ty         : 0.f;
    float wx0 = (x0 >= 0     && x0 < Ww)     ? (1.f - tx) : 0.f;
    float wx1 = (x0 + 1 >= 0 && x0 + 1 < Ww) ? tx         : 0.f;

    int z0c = min(max(z0, 0), Dd - 1), z1c = min(max(z0 + 1, 0), Dd - 1);
    int y0c = min(max(y0, 0), Hh - 1), y1c = min(max(y0 + 1, 0), Hh - 1);
    int x0c = min(max(x0, 0), Ww - 1), x1c = min(max(x0 + 1, 0), Ww - 1);

    int b00 = (z0c * Hh + y0c) * Ww;
    int b01 = (z0c * Hh + y1c) * Ww;
    int b10 = (z1c * Hh + y0c) * Ww;
    int b11 = (z1c * Hh + y1c) * Ww;

    off[0] = b00 + x0c;  w[0] = wz0 * wy0 * wx0;
    off[1] = b00 + x1c;  w[1] = wz0 * wy0 * wx1;
    off[2] = b01 + x0c;  w[2] = wz0 * wy1 * wx0;
    off[3] = b01 + x1c;  w[3] = wz0 * wy1 * wx1;
    off[4] = b10 + x0c;  w[4] = wz1 * wy0 * wx0;
    off[5] = b10 + x1c;  w[5] = wz1 * wy0 * wx1;
    off[6] = b11 + x0c;  w[6] = wz1 * wy1 * wx0;
    off[7] = b11 + x1c;  w[7] = wz1 * wy1 * wx1;
}

// pair layout: block (80,4), grid (Dd, Hh/4); thread owns x0=2*tx, x1=2*tx+1
#define PTX 80
#define PTY 4
__device__ __forceinline__ void pair_coords(int& tx, int& x0, int& y, int& z, int& idx) {
    tx = threadIdx.x;
    x0 = tx * 2;
    y = blockIdx.y * PTY + threadIdx.y;
    z = blockIdx.x;
    idx = (z * Hh + y) * Ww + x0;
}

__device__ __forceinline__ unsigned h2u(__half2 h) {
    return *reinterpret_cast<unsigned*>(&h);
}

// Write dup outputs for the pair (v0 at x0, v1 at x0+1, n* = value at x0+2).
__device__ __forceinline__ void write_pair(
        uint2* __restrict__ ozy, __half2* __restrict__ ox, int idx,
        float az0, float ay0, float ax0, float az1, float ay1, float ax1,
        float nz, float ny, float nx) {
    uint4 u;
    u.x = h2u(__floats2half2_rn(az0, ay0));
    u.y = h2u(__floats2half2_rn(az1, ay1));
    u.z = u.y;
    u.w = h2u(__floats2half2_rn(nz, ny));
    stcs4(ozy + idx, u);   // dup[idx] and dup[idx+1] in one STG.128... (keep cached: scratch is re-read)
    // scratch IS re-read by next kernel; use normal stores instead:
    ;
}

// Step 1 (packs fused), pair version.
__global__ void __launch_bounds__(320)
step1_fused(const float* __restrict__ flow0, const float* __restrict__ dvf,
            const float* __restrict__ src,
            uint2* __restrict__ ozy, __half2* __restrict__ ox,
            __half2* __restrict__ osrc, const float* __restrict__ rfp) {
    __shared__ float s[PTY][4][PTX];
    int tx, x0, y, z, idx; pair_coords(tx, x0, y, z, idx);
    int ty = threadIdx.y;
    float rf = __ldg(rfp);

    float2 fz = *(const float2*)(dvf + idx);
    float2 fy = *(const float2*)(dvf + idx + DHW);
    float2 fx = *(const float2*)(dvf + idx + 2 * DHW);
    float2 sv = *(const float2*)(src + idx);

    const float* f0y = flow0 + DHW;
    const float* f0x = flow0 + 2 * DHW;

    float az[2], ay[2], ax[2];
    #pragma unroll
    for (int p = 0; p < 2; p++) {
        float pfz = p ? fz.y : fz.x, pfy = p ? fy.y : fy.x, pfx = p ? fx.y : fx.x;
        float cz = fmaf(pfz * rf, SZC, (float)z * SZC - 0.5f);
        float cy = fmaf(pfy * rf, SYC, (float)y * SYC - 0.5f);
        float cx = fmaf(pfx * rf, SXC, (float)(x0 + p) * SXC - 0.5f);
        int off[8]; float w[8];
        make_corners(cz, cy, cx, off, w);
        float gz = pfz, gy = pfy, gx = pfx;
        #pragma unroll
        for (int k = 0; k < 8; k++) {
            gz = fmaf(w[k], __ldg(flow0 + off[k]), gz);
            gy = fmaf(w[k], __ldg(f0y   + off[k]), gy);
            gx = fmaf(w[k], __ldg(f0x   + off[k]), gx);
        }
        az[p] = gz; ay[p] = gy; ax[p] = gx;
    }

    s[ty][0][tx] = az[0]; s[ty][1][tx] = ay[0];
    s[ty][2][tx] = ax[0]; s[ty][3][tx] = sv.x;
    __syncthreads();
    bool last = (tx == PTX - 1);
    float nz = last ? az[1] : s[ty][0][tx + 1];
    float ny = last ? ay[1] : s[ty][1][tx + 1];
    float nx = last ? ax[1] : s[ty][2][tx + 1];
    float ns = last ? sv.y  : s[ty][3][tx + 1];

    uint4 u;
    u.x = h2u(__floats2half2_rn(az[0], ay[0]));
    u.y = h2u(__floats2half2_rn(az[1], ay[1]));
    u.z = u.y;
    u.w = h2u(__floats2half2_rn(nz, ny));
    *(uint4*)(ozy + idx) = u;

    uint2 v;
    v.x = h2u(__floats2half2_rn(ax[0], ax[1]));
    v.y = h2u(__floats2half2_rn(ax[1], nx));
    *(uint2*)(ox + idx) = v;

    uint2 sd;
    sd.x = h2u(__floats2half2_rn(sv.x, sv.y));
    sd.y = h2u(__floats2half2_rn(sv.y, ns));
    *(uint2*)(osrc + idx) = sd;
}

// Step 2: gather packed comp, add dvf, write dup-fp16. Pair version.
__global__ void __launch_bounds__(320)
step_packed(const uint2* __restrict__ czy, const __half2* __restrict__ cx_,
            const float* __restrict__ dvf,
            uint2* __restrict__ ozy, __half2* __restrict__ ox,
            const float* __restrict__ rfp) {
    __shared__ float s[PTY][3][PTX];
    int tx, x0, y, z, idx; pair_coords(tx, x0, y, z, idx);
    int ty = threadIdx.y;
    float rf = __ldg(rfp);

    float2 fz = *(const float2*)(dvf + idx);
    float2 fy = *(const float2*)(dvf + idx + DHW);
    float2 fx = *(const float2*)(dvf + idx + 2 * DHW);

    float az[2], ay[2], ax[2];
    #pragma unroll
    for (int p = 0; p < 2; p++) {
        float pfz = p ? fz.y : fz.x, pfy = p ? fy.y : fy.x, pfx = p ? fx.y : fx.x;
        float cz = fmaf(pfz * rf, SZC, (float)z * SZC - 0.5f);
        float cy = fmaf(pfy * rf, SYC, (float)y * SYC - 0.5f);
        float cx = fmaf(pfx * rf, SXC, (float)(x0 + p) * SXC - 0.5f);
        int ro[4]; float wyz[4], wa, wb;
        dup_corners(cz, cy, cx, ro, wyz, wa, wb);
        float vz, vy, vx;
        gather_packed(czy, cx_, ro, wyz, wa, wb, vz, vy, vx);
        az[p] = vz + pfz; ay[p] = vy + pfy; ax[p] = vx + pfx;
    }

    s[ty][0][tx] = az[0]; s[ty][1][tx] = ay[0]; s[ty][2][tx] = ax[0];
    __syncthreads();
    bool last = (tx == PTX - 1);
    float nz = last ? az[1] : s[ty][0][tx + 1];
    float ny = last ? ay[1] : s[ty][1][tx + 1];
    float nx = last ? ax[1] : s[ty][2][tx + 1];

    uint4 u;
    u.x = h2u(__floats2half2_rn(az[0], ay[0]));
    u.y = h2u(__floats2half2_rn(az[1], ay[1]));
    u.z = u.y;
    u.w = h2u(__floats2half2_rn(nz, ny));
    *(uint4*)(ozy + idx) = u;

    uint2 v;
    v.x = h2u(__floats2half2_rn(ax[0], ax[1]));
    v.y = h2u(__floats2half2_rn(ax[1], nx));
    *(uint2*)(ox + idx) = v;
}

// Final: pair version. out_flow fp32 planar via STG.64 .cs; deform dup-src gather.
__global__ void __launch_bounds__(320)
final_packed(const uint2* __restrict__ czy, const __half2* __restrict__ cx_,
             const float* __restrict__ ff, const __half2* __restrict__ srcd,
             float* __restrict__ out_deform, float* __restrict__ out_flow,
             const float* __restrict__ rfp) {
    int tx, x0, y, z, idx; pair_coords(tx, x0, y, z, idx);
    float rf = __ldg(rfp);

    float2 fz = *(const float2*)(ff + idx);
    float2 fy = *(const float2*)(ff + idx + DHW);
    float2 fx = *(const float2*)(ff + idx + 2 * DHW);

    float az[2], ay[2], ax[2], sd[2];
    #pragma unroll
    for (int p = 0; p < 2; p++) {
        float pfz = p ? fz.y : fz.x, pfy = p ? fy.y : fy.x, pfx = p ? fx.y : fx.x;
        float cz = fmaf(pfz * rf, SZC, (float)z * SZC - 0.5f);
        float cy = fmaf(pfy * rf, SYC, (float)y * SYC - 0.5f);
        float cx = fmaf(pfx * rf, SXC, (float)(x0 + p) * SXC - 0.5f);
        int ro[4]; float wyz[4], wa, wb;
        dup_corners(cz, cy, cx, ro, wyz, wa, wb);
        float vz, vy, vx;
        gather_packed(czy, cx_, ro, wyz, wa, wb, vz, vy, vx);
        az[p] = vz + pfz; ay[p] = vy + pfy; ax[p] = vx + pfx;

        float cz2 = fmaf(az[p] * rf, SZC, (float)z * SZC - 0.5f);
        float cy2 = fmaf(ay[p] * rf, SYC, (float)y * SYC - 0.5f);
        float cx2 = fmaf(ax[p] * rf, SXC, (float)(x0 + p) * SXC - 0.5f);
        int ro2[4]; float wyz2[4], wa2, wb2;
        dup_corners(cz2, cy2, cx2, ro2, wyz2, wa2, wb2);
        float sacc = 0.f;
        #pragma unroll
        for (int r = 0; r < 4; r++) {
            float2 c = __half22float2(__ldg(srcd + ro2[r]));
            sacc = fmaf(wyz2[r], fmaf(wb2, c.y, wa2 * c.x), sacc);
        }
        sd[p] = sacc;
    }

    stcs2(out_flow + idx,           az[0], az[1]);
    stcs2(out_flow + idx + DHW,     ay[0], ay[1]);
    stcs2(out_flow + idx + 2 * DHW, ax[0], ax[1]);
    stcs2(out_deform + idx,         sd[0], sd[1]);
}

extern "C" void kernel_launch(void* const* d_in, const int* in_sizes, int n_in,
                              void* d_out, int out_size) {
    const float* src        = (const float*)d_in[0];   // [1,1,D,H,W]
    const float* flow_list  = (const float*)d_in[1];   // [3,1,3,D,H,W]
    const float* final_flow = (const float*)d_in[2];   // [1,3,D,H,W]
    const float* rfp        = (const float*)d_in[3];   // scalar

    float* out_deform = (float*)d_out;          // [D*H*W]
    float* out_flow   = (float*)d_out + DHW;    // [3*D*H*W]

    uint2 *Pzy, *Qzy; __half2 *Px, *Qx, *Sd;
    cudaGetSymbolAddress((void**)&Pzy, g_Pzy);
    cudaGetSymbolAddress((void**)&Px,  g_Px);
    cudaGetSymbolAddress((void**)&Qzy, g_Qzy);
    cudaGetSymbolAddress((void**)&Qx,  g_Qx);
    cudaGetSymbolAddress((void**)&Sd,  g_S);

    dim3 block(PTX, PTY, 1);        // 320 threads
    dim3 grid(Dd, Hh / PTY, 1);     // 96 x 40

    step1_fused<<<grid, block>>>(flow_list, flow_list + 3 * DHW, src, Pzy, Px, Sd, rfp);
    step_packed<<<grid, block>>>(Pzy, Px, flow_list + 6 * DHW, Qzy, Qx, rfp);
    final_packed<<<grid, block>>>(Qzy, Qx, final_flow, Sd, out_deform, out_flow, rfp);
}

// round 13
// speedup vs baseline: 1.1215x; 1.1215x over previous
#include <cuda_runtime.h>
#include <cuda_fp16.h>

#define Dd 96
#define Hh 160
#define Ww 160
#define DHW (Dd*Hh*Ww)

// composed-flow scratch:
//  zy dup-pair: uint2 = { half2(z_i,y_i), half2(z_{i+1},y_{i+1}) }
//  x  dup-pair: half2 = ( x_i, x_{i+1} ),  neighbor clamped at W-1
__device__ uint2   g_Pzy[DHW];
__device__ __half2 g_Px [DHW];
__device__ uint2   g_Qzy[DHW];
__device__ __half2 g_Qx [DHW];
__device__ __half2 g_S  [DHW];   // src dup-pair fp16 (packed by step2)

// coord(v,s) = v*s/(s-1) - 0.5
#define SZC ((float)Dd / (float)(Dd - 1))
#define SYC ((float)Hh / (float)(Hh - 1))
#define SXC ((float)Ww / (float)(Ww - 1))

__device__ __forceinline__ void stcs(float* p, float v) {
    asm volatile("st.global.cs.f32 [%0], %1;" :: "l"(p), "f"(v) : "memory");
}

// Dup-pair corner setup: 4 row offsets (x folded in), row weights, pair weights.
__device__ __forceinline__ void dup_corners(float cz, float cy, float cx,
                                            int ro[4], float wyz[4],
                                            float& wa, float& wb) {
    float zf = floorf(cz), yf = floorf(cy), xf = floorf(cx);
    float tz = cz - zf, ty = cy - yf, tx = cx - xf;
    int z0 = (int)zf, y0 = (int)yf, x0 = (int)xf;

    float wz0 = (z0 >= 0     && z0 < Dd)     ? (1.f - tz) : 0.f;
    float wz1 = (z0 + 1 >= 0 && z0 + 1 < Dd) ? tz         : 0.f;
    float wy0 = (y0 >= 0     && y0 < Hh)     ? (1.f - ty) : 0.f;
    float wy1 = (y0 + 1 >= 0 && y0 + 1 < Hh) ? ty         : 0.f;
    float wx0 = (x0 >= 0     && x0 < Ww)     ? (1.f - tx) : 0.f;
    float wx1 = (x0 + 1 >= 0 && x0 + 1 < Ww) ? tx         : 0.f;

    wa = (x0 >= 0) ? wx0 : wx1;     // dup[0].lo == v[0] when x0 == -1
    wb = (x0 >= 0) ? wx1 : 0.f;
    int xc = min(max(x0, 0), Ww - 1);

    int z0c = min(max(z0, 0), Dd - 1), z1c = min(max(z0 + 1, 0), Dd - 1);
    int y0c = min(max(y0, 0), Hh - 1), y1c = min(max(y0 + 1, 0), Hh - 1);

    ro[0] = (z0c * Hh + y0c) * Ww + xc;  wyz[0] = wz0 * wy0;
    ro[1] = (z0c * Hh + y1c) * Ww + xc;  wyz[1] = wz0 * wy1;
    ro[2] = (z1c * Hh + y0c) * Ww + xc;  wyz[2] = wz1 * wy0;
    ro[3] = (z1c * Hh + y1c) * Ww + xc;  wyz[3] = wz1 * wy1;
}

// Gather packed comp: (z,y) from zy dup-half4, x from dup-half2.
__device__ __forceinline__ void gather_packed(
        const uint2* __restrict__ zy, const __half2* __restrict__ px,
        const int ro[4], const float wyz[4], float wa, float wb,
        float& vz, float& vy, float& vx) {
    vz = 0.f; vy = 0.f; vx = 0.f;
    #pragma unroll
    for (int r = 0; r < 4; r++) {
        uint2 u = __ldg(zy + ro[r]);
        float2 a = __half22float2(*reinterpret_cast<__half2*>(&u.x));
        float2 b = __half22float2(*reinterpret_cast<__half2*>(&u.y));
        vz = fmaf(wyz[r], fmaf(wb, b.x, wa * a.x), vz);
        vy = fmaf(wyz[r], fmaf(wb, b.y, wa * a.y), vy);
        float2 c = __half22float2(__ldg(px + ro[r]));
        vx = fmaf(wyz[r], fmaf(wb, c.y, wa * c.x), vx);
    }
}

// fp32 planar 8-corner setup (for flow0 gather in step1)
__device__ __forceinline__ void make_corners(float cz, float cy, float cx,
                                             int off[8], float w[8]) {
    float z0f = floorf(cz), y0f = floorf(cy), x0f = floorf(cx);
    float tz = cz - z0f, ty = cy - y0f, tx = cx - x0f;
    int z0 = (int)z0f, y0 = (int)y0f, x0 = (int)x0f;

    float wz0 = (z0 >= 0     && z0 < Dd)     ? (1.f - tz) : 0.f;
    float wz1 = (z0 + 1 >= 0 && z0 + 1 < Dd) ? tz         : 0.f;
    float wy0 = (y0 >= 0     && y0 < Hh)     ? (1.f - ty) : 0.f;
    float wy1 = (y0 + 1 >= 0 && y0 + 1 < Hh) ? ty         : 0.f;
    float wx0 = (x0 >= 0     && x0 < Ww)     ? (1.f - tx) : 0.f;
    float wx1 = (x0 + 1 >= 0 && x0 + 1 < Ww) ? tx         : 0.f;

    int z0c = min(max(z0, 0), Dd - 1), z1c = min(max(z0 + 1, 0), Dd - 1);
    int y0c = min(max(y0, 0), Hh - 1), y1c = min(max(y0 + 1, 0), Hh - 1);
    int x0c = min(max(x0, 0), Ww - 1), x1c = min(max(x0 + 1, 0), Ww - 1);

    int b00 = (z0c * Hh + y0c) * Ww;
    int b01 = (z0c * Hh + y1c) * Ww;
    int b10 = (z1c * Hh + y0c) * Ww;
    int b11 = (z1c * Hh + y1c) * Ww;

    off[0] = b00 + x0c;  w[0] = wz0 * wy0 * wx0;
    off[1] = b00 + x1c;  w[1] = wz0 * wy0 * wx1;
    off[2] = b01 + x0c;  w[2] = wz0 * wy1 * wx0;
    off[3] = b01 + x1c;  w[3] = wz0 * wy1 * wx1;
    off[4] = b10 + x0c;  w[4] = wz1 * wy0 * wx0;
    off[5] = b10 + x1c;  w[5] = wz1 * wy0 * wx1;
    off[6] = b11 + x0c;  w[6] = wz1 * wy1 * wx0;
    off[7] = b11 + x1c;  w[7] = wz1 * wy1 * wx1;
}

// block (160,2): one (z,y) row per thread-row. grid (Hh/2, Dd) — adjacent
// scheduled blocks share z slices (L2-friendly).
__device__ __forceinline__ void row_coords(int& x, int& y, int& z, int& idx) {
    x = threadIdx.x;
    y = blockIdx.x * 2 + threadIdx.y;
    z = blockIdx.y;
    idx = (z * Hh + y) * Ww + x;
}

__device__ __forceinline__ unsigned h2u(__half2 h) {
    return *reinterpret_cast<unsigned*>(&h);
}

// Step 1: gather flow0 planar fp32, add dvf, write dup-fp16.
__global__ void __launch_bounds__(320)
step1_fused(const float* __restrict__ flow0, const float* __restrict__ dvf,
            uint2* __restrict__ ozy, __half2* __restrict__ ox,
            const float* __restrict__ rfp) {
    __shared__ float s[2][3][Ww];
    int x, y, z, idx; row_coords(x, y, z, idx);
    int ty = threadIdx.y;
    float rf = __ldg(rfp);

    float fz = dvf[idx], fy = dvf[idx + DHW], fx = dvf[idx + 2 * DHW];

    float cz = fmaf(fz * rf, SZC, (float)z * SZC - 0.5f);
    float cy = fmaf(fy * rf, SYC, (float)y * SYC - 0.5f);
    float cx = fmaf(fx * rf, SXC, (float)x * SXC - 0.5f);

    int off[8]; float w[8];
    make_corners(cz, cy, cx, off, w);

    float az = fz, ay = fy, ax = fx;
    const float* f0y = flow0 + DHW;
    const float* f0x = flow0 + 2 * DHW;
    #pragma unroll
    for (int k = 0; k < 8; k++) {
        az = fmaf(w[k], __ldg(flow0 + off[k]), az);
        ay = fmaf(w[k], __ldg(f0y   + off[k]), ay);
        ax = fmaf(w[k], __ldg(f0x   + off[k]), ax);
    }

    s[ty][0][x] = az; s[ty][1][x] = ay; s[ty][2][x] = ax;
    __syncthreads();
    int xn = (x < Ww - 1) ? x + 1 : x;
    uint2 u;
    u.x = h2u(__floats2half2_rn(az, ay));
    u.y = h2u(__floats2half2_rn(s[ty][0][xn], s[ty][1][xn]));
    ozy[idx] = u;
    ox[idx]  = __floats2half2_rn(ax, s[ty][2][xn]);
}

// Step 2: gather packed comp, add dvf, write dup-fp16; also pack src.
__global__ void __launch_bounds__(320)
step2_fused(const uint2* __restrict__ czy, const __half2* __restrict__ cx_,
            const float* __restrict__ dvf, const float* __restrict__ src,
            uint2* __restrict__ ozy, __half2* __restrict__ ox,
            __half2* __restrict__ osrc, const float* __restrict__ rfp) {
    __shared__ float s[2][4][Ww];
    int x, y, z, idx; row_coords(x, y, z, idx);
    int ty = threadIdx.y;
    float rf = __ldg(rfp);

    float fz = dvf[idx], fy = dvf[idx + DHW], fx = dvf[idx + 2 * DHW];
    float sv = __ldg(src + idx);

    float cz = fmaf(fz * rf, SZC, (float)z * SZC - 0.5f);
    float cy = fmaf(fy * rf, SYC, (float)y * SYC - 0.5f);
    float cx = fmaf(fx * rf, SXC, (float)x * SXC - 0.5f);

    int ro[4]; float wyz[4], wa, wb;
    dup_corners(cz, cy, cx, ro, wyz, wa, wb);

    float vz, vy, vx;
    gather_packed(czy, cx_, ro, wyz, wa, wb, vz, vy, vx);

    float az = vz + fz, ay = vy + fy, ax = vx + fx;

    s[ty][0][x] = az; s[ty][1][x] = ay; s[ty][2][x] = ax; s[ty][3][x] = sv;
    __syncthreads();
    int xn = (x < Ww - 1) ? x + 1 : x;
    uint2 u;
    u.x = h2u(__floats2half2_rn(az, ay));
    u.y = h2u(__floats2half2_rn(s[ty][0][xn], s[ty][1][xn]));
    ozy[idx]  = u;
    ox[idx]   = __floats2half2_rn(ax, s[ty][2][xn]);
    osrc[idx] = __floats2half2_rn(sv, s[ty][3][xn]);
}

// Final: composed3 = gather(comp) + ff -> out_flow fp32 planar;
//        deform    = dup-gather of fp16 src at base + composed3*rf
__global__ void __launch_bounds__(320)
final_packed(const uint2* __restrict__ czy, const __half2* __restrict__ cx_,
             const float* __restrict__ ff, const __half2* __restrict__ srcd,
             float* __restrict__ out_deform, float* __restrict__ out_flow,
             const float* __restrict__ rfp) {
    int x, y, z, idx; row_coords(x, y, z, idx);
    float rf = __ldg(rfp);

    float fz = ff[idx], fy = ff[idx + DHW], fx = ff[idx + 2 * DHW];

    float cz = fmaf(fz * rf, SZC, (float)z * SZC - 0.5f);
    float cy = fmaf(fy * rf, SYC, (float)y * SYC - 0.5f);
    float cx = fmaf(fx * rf, SXC, (float)x * SXC - 0.5f);

    int ro[4]; float wyz[4], wa, wb;
    dup_corners(cz, cy, cx, ro, wyz, wa, wb);

    float vz, vy, vx;
    gather_packed(czy, cx_, ro, wyz, wa, wb, vz, vy, vx);

    float az = vz + fz, ay = vy + fy, ax = vx + fx;
    stcs(out_flow + idx,           az);
    stcs(out_flow + idx + DHW,     ay);
    stcs(out_flow + idx + 2 * DHW, ax);

    float cz2 = fmaf(az * rf, SZC, (float)z * SZC - 0.5f);
    float cy2 = fmaf(ay * rf, SYC, (float)y * SYC - 0.5f);
    float cx2 = fmaf(ax * rf, SXC, (float)x * SXC - 0.5f);

    int ro2[4]; float wyz2[4], wa2, wb2;
    dup_corners(cz2, cy2, cx2, ro2, wyz2, wa2, wb2);

    float sacc = 0.f;
    #pragma unroll
    for (int r = 0; r < 4; r++) {
        float2 c = __half22float2(__ldg(srcd + ro2[r]));
        sacc = fmaf(wyz2[r], fmaf(wb2, c.y, wa2 * c.x), sacc);
    }
    stcs(out_deform + idx, sacc);
}

extern "C" void kernel_launch(void* const* d_in, const int* in_sizes, int n_in,
                              void* d_out, int out_size) {
    const float* src        = (const float*)d_in[0];   // [1,1,D,H,W]
    const float* flow_list  = (const float*)d_in[1];   // [3,1,3,D,H,W]
    const float* final_flow = (const float*)d_in[2];   // [1,3,D,H,W]
    const float* rfp        = (const float*)d_in[3];   // scalar

    float* out_deform = (float*)d_out;          // [D*H*W]
    float* out_flow   = (float*)d_out + DHW;    // [3*D*H*W]

    uint2 *Pzy, *Qzy; __half2 *Px, *Qx, *Sd;
    cudaGetSymbolAddress((void**)&Pzy, g_Pzy);
    cudaGetSymbolAddress((void**)&Px,  g_Px);
    cudaGetSymbolAddress((void**)&Qzy, g_Qzy);
    cudaGetSymbolAddress((void**)&Qx,  g_Qx);
    cudaGetSymbolAddress((void**)&Sd,  g_S);

    dim3 block(Ww, 2, 1);           // 320 threads, warps x-compact
    dim3 grid(Hh / 2, Dd, 1);       // 80 x 96; adjacent blocks share z

    // step1: comp = flow_list[0] fp32 planar, dvf = flow_list[1] -> P
    step1_fused<<<grid, block>>>(flow_list, flow_list + 3 * DHW, Pzy, Px, rfp);
    // step2: comp = P, dvf = flow_list[2] -> Q; src -> Sd
    step2_fused<<<grid, block>>>(Pzy, Px, flow_list + 6 * DHW, src, Qzy, Qx, Sd, rfp);
    // final: comp = Q, ff = final_flow, src = dup-fp16
    final_packed<<<grid, block>>>(Qzy, Qx, final_flow, Sd, out_deform, out_flow, rfp);
}